// round 11
// baseline (speedup 1.0000x reference)
#include <cuda_runtime.h>

// FullSpikeFunction: LIF recurrence with adaptive threshold + refractory.
// x[B=16, T=4096, N=1024] fp32 -> z[B, T, N] fp32.
//
// Numerics contract (validated rel_err==0.0 in R7/R8/R10): XLA fuses the LHS
// fmul of each fadd/fsub (one-use only); the two-use spike crumb is unfused:
//   m  = fl(0.1f*x); s = fmaf(0.9f,u,m); u = fmaf(-z_prev,rg,s)
//   v  = fl(u-b); d = fl(v-1)
//   crumb: zb = fl(fl(-0.5f*fl(d*d))*0.3f); zsp = fl(fl(1-zb)+zb)
//   z1 = (v<1) ? zsp : 1.0f ; z = (v>0 && q==0) ? z1 : 0.0f   (z = 1 +/- ulp)
//   q  = max(0,q-1) + (z>=1.0f ? 5 : 0)   // f32->s32 trunc semantics
//   b  = fmaf(0.95f,b, fl(fl(0.05f*z)*tg))
// (d and 1-zb are computed as FFMA with +/-1.0 immediate multiplier: exact,
//  and FFMA-imm runs at rt_SMSP=1, 2x FADD throughput.)
//
// R10 post-mortem: 64-thread blocks put warps only on SMSP 0/1 (SMSP = wid%4)
// -> 2 warps/SMSP busy, 2 SMSPs idle, ~133 cyc/step. Fix: 128 blocks x 128
// threads = 1 block/SM, 4 warps on 4 SMSPs, exactly 1 warp/SMSP.

namespace {
constexpr int kB = 16;
constexpr int kT = 4096;
constexpr int kN = 1024;
constexpr int kU = 16;            // time steps per prefetch group
constexpr int kThreads = 128;
constexpr int kLanes = kB * kN;                      // 16384
constexpr int kBlocks = kLanes / kThreads;           // 128
}  // namespace

// One time-step, exact reference rounding.
__device__ __forceinline__ float lif_step(float xt, float& u, float& bb,
                                          int& q, float& zprev,
                                          float rg, float tg)
{
    const float m = __fmul_rn(0.1f, xt);
    const float s = __fmaf_rn(0.9f, u, m);
    u = __fmaf_rn(-zprev, rg, s);
    const float v = __fadd_rn(u, -bb);

    // unmasked crumb chain (FFMA-imm forms are exact and 2x throughput)
    const float d  = __fmaf_rn(v, 1.0f, -1.0f);          // fl(v - 1)
    const float zb = __fmul_rn(__fmul_rn(-0.5f, __fmul_rn(d, d)), 0.3f);
    const float t1 = __fmaf_rn(zb, -1.0f, 1.0f);         // fl(1 - zb)
    const float zsp = __fadd_rn(t1, zb);

    // |v|>=1 with v>0 => zb masked to 0 in reference => z = 1.0 exactly
    const float z1 = (v < 1.0f) ? zsp : 1.0f;
    const bool fire = (v > 0.0f) && (q == 0);
    const float z = fire ? z1 : 0.0f;

    q = max(q - 1, 0);
    q += (z >= 1.0f) ? 5 : 0;

    bb = __fmaf_rn(0.95f, bb, __fmul_rn(__fmul_rn(0.05f, z), tg));
    zprev = z;
    return z;
}

__global__ __launch_bounds__(kThreads, 1)
void full_spike_kernel(const float* __restrict__ x,
                       const float* __restrict__ reset_gamma,
                       const float* __restrict__ thr_gamma,
                       const float* __restrict__ u0,
                       const float* __restrict__ b0,
                       float* __restrict__ out)
{
    const int idx = blockIdx.x * kThreads + threadIdx.x;   // 0 .. kLanes-1
    if (idx >= kLanes) return;
    const int n = idx & (kN - 1);
    const int b = idx >> 10;

    const size_t base = (size_t)b * kT * kN + n;
    const float* xp = x + base;
    float* zp = out + base;

    float u  = u0[n];
    float bb = b0[n];
    const float rg = reset_gamma[n];
    const float tg = thr_gamma[n];
    int   q = 0;
    float zprev = 0.0f;

    float bufA[kU], bufB[kU];

    // prime bufA with group 0
    #pragma unroll
    for (int i = 0; i < kU; ++i)
        bufA[i] = __ldcs(xp + (size_t)i * kN);

    const int ngroups = kT / kU;   // 256 (even)
    for (int g = 0; g < ngroups; g += 2) {
        // half A: prefetch group g+1 into bufB, consume bufA
        {
            const float* xn = xp + (size_t)(g + 1) * kU * kN;
            #pragma unroll
            for (int i = 0; i < kU; ++i)
                bufB[i] = __ldcs(xn + (size_t)i * kN);
        }
        {
            float* zg = zp + (size_t)g * kU * kN;
            #pragma unroll
            for (int i = 0; i < kU; ++i)
                __stcs(zg + (size_t)i * kN,
                       lif_step(bufA[i], u, bb, q, zprev, rg, tg));
        }

        // half B: prefetch group g+2 into bufA, consume bufB
        if (g + 2 < ngroups) {
            const float* xn = xp + (size_t)(g + 2) * kU * kN;
            #pragma unroll
            for (int i = 0; i < kU; ++i)
                bufA[i] = __ldcs(xn + (size_t)i * kN);
        }
        {
            float* zg = zp + (size_t)(g + 1) * kU * kN;
            #pragma unroll
            for (int i = 0; i < kU; ++i)
                __stcs(zg + (size_t)i * kN,
                       lif_step(bufB[i], u, bb, q, zprev, rg, tg));
        }
    }
}

extern "C" void kernel_launch(void* const* d_in, const int* in_sizes, int n_in,
                              void* d_out, int out_size)
{
    const float* x           = (const float*)d_in[0];
    const float* reset_gamma = (const float*)d_in[1];
    const float* thr_gamma   = (const float*)d_in[2];
    const float* u0          = (const float*)d_in[3];
    const float* b0          = (const float*)d_in[4];
    float* out = (float*)d_out;

    full_spike_kernel<<<kBlocks, kThreads>>>(x, reset_gamma, thr_gamma, u0, b0, out);
}

// round 12
// speedup vs baseline: 1.0258x; 1.0258x over previous
#include <cuda_runtime.h>

// FullSpikeFunction: LIF recurrence with adaptive threshold + refractory.
// x[B=16, T=4096, N=1024] fp32 -> z[B, T, N] fp32.
//
// Numerics contract (validated rel_err==0.0 R7/R8/R10/R11): XLA fuses the LHS
// fmul of each fadd/fsub (one-use only); the two-use spike crumb is unfused:
//   m  = fl(0.1f*x); s = fmaf(0.9f,u,m); u = fmaf(-z_prev,rg,s)
//   v  = fl(u-b); d = fl(v-1)
//   zb = fl(fl(-0.5f*fl(d*d))*0.3f); zsp = fl(fl(1-zb)+zb)
//   z1 = (v<1) ? zsp : 1.0f ; z = (v>0 && q==0) ? z1 : 0.0f  (z = 1 +/- ulp)
//   refr-inc (z>=1)  ==  fire && (v>=1 || zsp>=1)   [proved exact; lets all
//     FSETPs issue in parallel after v/zsp instead of serially after z]
//   q  = max(0,q-1) + (refr ? 5 : 0)
//   b  = fmaf(0.95f,b, fl(fl(0.05f*z)*tg))
//
// Perf model (R8/R10/R11 post-mortems): per-warp static schedule ~165 cyc/step
// at w=1 despite a ~35-cyc true chain and ~28 slots. Gap attributed to ptxas
// reusing LDG dest regs under its occupancy heuristic (regs=56-72 < needed),
// collapsing prefetch MLP from 16 to ~4 -> ~140 cyc/step of exposed DRAM
// latency. Fixes: __launch_bounds__(64,1) lifts the reg ceiling to 255 so the
// 32 buffer regs live independently (MLP=16), plus the shorter q-chain.
// Config stays at the measured-best 256 blocks x 64 thr (2 warps/SMSP).

namespace {
constexpr int kB = 16;
constexpr int kT = 4096;
constexpr int kN = 1024;
constexpr int kU = 16;            // time steps per prefetch group
constexpr int kThreads = 64;
constexpr int kLanes = kB * kN;                      // 16384
constexpr int kBlocks = kLanes / kThreads;           // 256
}  // namespace

// One time-step, exact reference rounding.
__device__ __forceinline__ float lif_step(float xt, float& u, float& bb,
                                          int& q, float& zprev,
                                          float rg, float tg)
{
    const float m = __fmul_rn(0.1f, xt);
    const float s = __fmaf_rn(0.9f, u, m);
    u = __fmaf_rn(-zprev, rg, s);
    const float v = __fadd_rn(u, -bb);

    // unmasked crumb chain
    const float d   = __fadd_rn(v, -1.0f);
    const float zb  = __fmul_rn(__fmul_rn(-0.5f, __fmul_rn(d, d)), 0.3f);
    const float zsp = __fadd_rn(__fadd_rn(1.0f, -zb), zb);

    // parallel predicates (all depend only on v / zsp / q)
    const bool p_lt1  = (v < 1.0f);
    const bool p_pos  = (v > 0.0f);
    const bool p_spge = (zsp >= 1.0f);
    const bool fire   = p_pos && (q == 0);

    const float z1 = p_lt1 ? zsp : 1.0f;   // |v|>=1 & fire => z = 1.0 exactly
    const float z  = fire ? z1 : 0.0f;

    // refractory increment: (z >= 1.0f) == fire && (v>=1 || zsp>=1)
    const bool refr = fire && (p_spge || !p_lt1);
    q = max(q - 1, 0) + (refr ? 5 : 0);

    bb = __fmaf_rn(0.95f, bb, __fmul_rn(__fmul_rn(0.05f, z), tg));
    zprev = z;
    return z;
}

__global__ __launch_bounds__(kThreads, 1)
void full_spike_kernel(const float* __restrict__ x,
                       const float* __restrict__ reset_gamma,
                       const float* __restrict__ thr_gamma,
                       const float* __restrict__ u0,
                       const float* __restrict__ b0,
                       float* __restrict__ out)
{
    const int idx = blockIdx.x * kThreads + threadIdx.x;   // 0 .. kLanes-1
    if (idx >= kLanes) return;
    const int n = idx & (kN - 1);
    const int b = idx >> 10;

    const size_t base = (size_t)b * kT * kN + n;
    const float* xp = x + base;
    float* zp = out + base;

    float u  = u0[n];
    float bb = b0[n];
    const float rg = reset_gamma[n];
    const float tg = thr_gamma[n];
    int   q = 0;
    float zprev = 0.0f;

    float bufA[kU], bufB[kU];

    // prime bufA with group 0
    #pragma unroll
    for (int i = 0; i < kU; ++i)
        bufA[i] = __ldcs(xp + (size_t)i * kN);

    const int ngroups = kT / kU;   // 256 (even)
    for (int g = 0; g < ngroups; g += 2) {
        // half A: prefetch group g+1 into bufB, consume bufA
        {
            const float* xn = xp + (size_t)(g + 1) * kU * kN;
            #pragma unroll
            for (int i = 0; i < kU; ++i)
                bufB[i] = __ldcs(xn + (size_t)i * kN);
        }
        {
            float* zg = zp + (size_t)g * kU * kN;
            #pragma unroll
            for (int i = 0; i < kU; ++i)
                __stcs(zg + (size_t)i * kN,
                       lif_step(bufA[i], u, bb, q, zprev, rg, tg));
        }

        // half B: prefetch group g+2 into bufA, consume bufB
        if (g + 2 < ngroups) {
            const float* xn = xp + (size_t)(g + 2) * kU * kN;
            #pragma unroll
            for (int i = 0; i < kU; ++i)
                bufA[i] = __ldcs(xn + (size_t)i * kN);
        }
        {
            float* zg = zp + (size_t)(g + 1) * kU * kN;
            #pragma unroll
            for (int i = 0; i < kU; ++i)
                __stcs(zg + (size_t)i * kN,
                       lif_step(bufB[i], u, bb, q, zprev, rg, tg));
        }
    }
}

extern "C" void kernel_launch(void* const* d_in, const int* in_sizes, int n_in,
                              void* d_out, int out_size)
{
    const float* x           = (const float*)d_in[0];
    const float* reset_gamma = (const float*)d_in[1];
    const float* thr_gamma   = (const float*)d_in[2];
    const float* u0          = (const float*)d_in[3];
    const float* b0          = (const float*)d_in[4];
    float* out = (float*)d_out;

    full_spike_kernel<<<kBlocks, kThreads>>>(x, reset_gamma, thr_gamma, u0, b0, out);
}

// round 14
// speedup vs baseline: 1.6721x; 1.6301x over previous
#include <cuda_runtime.h>

// FullSpikeFunction: LIF recurrence with adaptive threshold + refractory.
// x[B=16, T=4096, N=1024] fp32 -> z[B, T, N] fp32.
//
// (Resubmission: R13 bench died to container infra flake before compile/run.
// The cp.async/SMEM-ring theory from the R12 post-mortem is untested; no
// evidence-driven change to make.)
//
// Numerics contract (validated rel_err==0.0 R7/R8/R10/R11/R12) -- see lif_step.
//
// Perf history: all register-double-buffer variants stall 100-140 cyc/step
// (~28 issue slots vs ~25-cyc chain) because ptxas never keeps 32 buffer regs
// live; loads sink to their uses and expose DRAM latency. Structural fix:
// cp.async -> SMEM 3-stage ring (zero register cost, prefetch distance =
// 2 groups ~ 1000+ cyc > 577-cyc DRAM latency), consume via conflict-free
// LDS. 128 blocks x 128 threads = 1 warp/SMSP on 128 SMs (optimal once
// latency is hidden and issue slots/chain bind).

namespace {
constexpr int kB = 16;
constexpr int kT = 4096;
constexpr int kN = 1024;
constexpr int kU = 16;                     // time steps per group
constexpr int kThreads = 128;
constexpr int kLanes = kB * kN;            // 16384
constexpr int kBlocks = kLanes / kThreads; // 128
constexpr int kGroups = kT / kU;           // 256
constexpr int kBufFloats = kU * kThreads;  // 2048 floats = 8 KB per stage
}  // namespace

__device__ __forceinline__ unsigned smem_u32(const void* p) {
    unsigned r;
    asm("{ .reg .u64 t; cvta.to.shared.u64 t, %1; cvt.u32.u64 %0, t; }"
        : "=r"(r) : "l"(p));
    return r;
}

// One time-step, exact reference rounding (validated rel_err == 0.0).
__device__ __forceinline__ float lif_step(float xt, float& u, float& bb,
                                          int& q, float& zprev,
                                          float rg, float tg)
{
    const float m = __fmul_rn(0.1f, xt);
    const float s = __fmaf_rn(0.9f, u, m);
    u = __fmaf_rn(-zprev, rg, s);
    const float v = __fadd_rn(u, -bb);

    // unmasked crumb chain (two-use zb stays unfused in XLA)
    const float d   = __fadd_rn(v, -1.0f);
    const float zb  = __fmul_rn(__fmul_rn(-0.5f, __fmul_rn(d, d)), 0.3f);
    const float zsp = __fadd_rn(__fadd_rn(1.0f, -zb), zb);

    const bool p_lt1  = (v < 1.0f);
    const bool p_pos  = (v > 0.0f);
    const bool p_spge = (zsp >= 1.0f);
    const bool fire   = p_pos && (q == 0);

    const float z1 = p_lt1 ? zsp : 1.0f;   // |v|>=1 & fire => z = 1.0 exactly
    const float z  = fire ? z1 : 0.0f;

    // refractory increment: (z >= 1.0f) == fire && (zsp>=1 || v>=1)
    const bool refr = fire && (p_spge || !p_lt1);
    q = max(q - 1, 0) + (refr ? 5 : 0);

    bb = __fmaf_rn(0.95f, bb, __fmul_rn(__fmul_rn(0.05f, z), tg));
    zprev = z;
    return z;
}

__global__ __launch_bounds__(kThreads, 1)
void full_spike_kernel(const float* __restrict__ x,
                       const float* __restrict__ reset_gamma,
                       const float* __restrict__ thr_gamma,
                       const float* __restrict__ u0,
                       const float* __restrict__ b0,
                       float* __restrict__ out)
{
    __shared__ __align__(16) float buf[3][kBufFloats];   // 24 KB ring

    const int tid = threadIdx.x;
    const int idx = blockIdx.x * kThreads + tid;   // 0 .. kLanes-1
    const int n   = idx & (kN - 1);
    const int b   = idx >> 10;
    const int n0  = (blockIdx.x & 7) * kThreads;   // block's n base (uniform)

    // block-uniform gmem base for cp.async source rows
    const float* xg = x + (size_t)b * kT * kN + n0;
    float* zp = out + (size_t)b * kT * kN + n;

    float u  = u0[n];
    float bb = b0[n];
    const float rg = reset_gamma[n];
    const float tg = thr_gamma[n];
    int   q = 0;
    float zprev = 0.0f;

    // Per-thread cp.async chunk map: group = 16 rows x 512 B = 128 thr x 4 x 16 B.
    // chunk c = tid + 128*k : row = c>>5, byte col = (c&31)*16.
    const unsigned sbase[3] = { smem_u32(&buf[0][0]), smem_u32(&buf[1][0]),
                                smem_u32(&buf[2][0]) };

    auto issue_group = [&](int g, int stage) {
        const float* src = xg + (size_t)g * kU * kN;
        const unsigned dst = sbase[stage];
        #pragma unroll
        for (int k = 0; k < 4; ++k) {
            const int c   = tid + kThreads * k;
            const int row = c >> 5;
            const int col = (c & 31) * 16;
            const unsigned d = dst + row * (kThreads * 4) + col;
            const char* s = (const char*)(src + (size_t)row * kN) + col;
            asm volatile("cp.async.cg.shared.global [%0], [%1], 16;"
                         :: "r"(d), "l"(s) : "memory");
        }
        asm volatile("cp.async.commit_group;" ::: "memory");
    };

    // Prime two groups (stages 0 and 1).
    issue_group(0, 0);
    issue_group(1, 1);

    int st_cons = 0;   // stage holding group g
    int st_load = 2;   // stage to load group g+2 into
    for (int g = 0; g < kGroups; ++g) {
        // One commit per iteration (FIFO): wait_group 1 => group g's data landed.
        asm volatile("cp.async.wait_group 1;" ::: "memory");
        __syncthreads();   // all threads done with stage st_load's old contents

        if (g + 2 < kGroups) issue_group(g + 2, st_load);
        else asm volatile("cp.async.commit_group;" ::: "memory");  // empty group

        const float* bc = &buf[st_cons][0];
        float* zg = zp + (size_t)g * kU * kN;
        #pragma unroll
        for (int i = 0; i < kU; ++i) {
            const float xt = bc[i * kThreads + tid];
            __stcs(zg + (size_t)i * kN,
                   lif_step(xt, u, bb, q, zprev, rg, tg));
        }

        // rotate ring
        st_cons = (st_cons == 2) ? 0 : st_cons + 1;
        st_load = (st_load == 2) ? 0 : st_load + 1;
    }
}

extern "C" void kernel_launch(void* const* d_in, const int* in_sizes, int n_in,
                              void* d_out, int out_size)
{
    const float* x           = (const float*)d_in[0];
    const float* reset_gamma = (const float*)d_in[1];
    const float* thr_gamma   = (const float*)d_in[2];
    const float* u0          = (const float*)d_in[3];
    const float* b0          = (const float*)d_in[4];
    float* out = (float*)d_out;

    full_spike_kernel<<<kBlocks, kThreads>>>(x, reset_gamma, thr_gamma, u0, b0, out);
}